// round 11
// baseline (speedup 1.0000x reference)
#include <cuda_runtime.h>
#include <cuda_fp16.h>
#include <math.h>
#include <stdint.h>

// ---------------------------------------------------------------------------
// MMD^2 (RBF, gamma=1), 8192x16 fp32, via mma.sync.m16n8k16 fp16 (sm_100 base).
//
// Coords scaled by sqrt(2*log2e), split x = hi + lo (fp16).
// K = 48: A chunks [hi | lo | hi], B chunks [hi | hi | lo]
//   => acc = 2*log2e*dot(a,b)  (lo*lo dropped, ~2^-22 rel)
// Norm terms applied in the epilogue: k = ex2(acc) * ena * enb with
// ena/enb = exp2(-0.5|x_s|^2) per tile row (SMEM).
// n-dim split in two 32-col halves; half-B's MMA mainloop interleaves
// half-A's MUFU epilogue (tensor + MUFU pipe overlap in-warp).
// Final reduction fused into the last CTA (threadfence-reduction pattern).
// ---------------------------------------------------------------------------

#define NSRC   8192
#define D      16
#define NP     16384
#define TILE   128
#define TB     (NP / TILE)                 // 128
#define NBLK   (TB * (TB + 1) / 2)         // 8256
#define SQ2L   1.6986436004918308f         // sqrt(2*log2(e))
#define ROWB   112                         // 96B data + 16B pad (conflict-free)
#define NKC    3                           // K = 48, chunks of 16
#define ATILEB (TILE * ROWB)               // 14336 B per tile side

// per point: u0,u1 = hi(16 fp16), u2,u3 = lo
__device__ uint4  g_S[NP * 4];
__device__ float  g_N[NP];                 // -0.5*|x_s|^2
__device__ double g_part[NBLK];
__device__ unsigned int g_count;

// ---------------- helpers ----------------
__device__ __forceinline__ float ex2(float x) {
    float r; asm("ex2.approx.f32 %0, %1;" : "=f"(r) : "f"(x)); return r;
}
__device__ __forceinline__ uint32_t smem_u32(const void* p) {
    uint32_t a;
    asm("{ .reg .u64 t; cvta.to.shared.u64 t, %1; cvt.u32.u64 %0, t; }"
        : "=r"(a) : "l"(p));
    return a;
}
__device__ __forceinline__ void ldsm4(uint32_t* r, uint32_t addr) {
    asm volatile("ldmatrix.sync.aligned.m8n8.x4.shared.b16 {%0,%1,%2,%3}, [%4];"
                 : "=r"(r[0]), "=r"(r[1]), "=r"(r[2]), "=r"(r[3]) : "r"(addr));
}
__device__ __forceinline__ void mma16816(float* c, const uint32_t* a,
                                         uint32_t b0, uint32_t b1) {
    asm volatile("mma.sync.aligned.m16n8k16.row.col.f32.f16.f16.f32 "
                 "{%0,%1,%2,%3}, {%4,%5,%6,%7}, {%8,%9}, {%0,%1,%2,%3};"
                 : "+f"(c[0]), "+f"(c[1]), "+f"(c[2]), "+f"(c[3])
                 : "r"(a[0]), "r"(a[1]), "r"(a[2]), "r"(a[3]), "r"(b0), "r"(b1));
}
__device__ __forceinline__ int tri_row_start(int t) {
    return t * TB - ((t * (t - 1)) >> 1);
}

// ---------------------------------------------------------------------------
// Kernel 1: scale, fp16 hi/lo split, norm term. Also resets g_count.
// ---------------------------------------------------------------------------
__global__ void __launch_bounds__(128) split_kernel(const float* __restrict__ src,
                                                    const float* __restrict__ tgt) {
    if (blockIdx.x == 0 && threadIdx.x == 0) g_count = 0u;
    int p = blockIdx.x * 128 + threadIdx.x;
    if (p >= NP) return;
    const float* x = (p < NSRC) ? (src + (size_t)p * D) : (tgt + (size_t)(p - NSRC) * D);

    uint4 u[4];
    __half* hi = (__half*)&u[0];
    __half* lo = (__half*)&u[2];

    float ns = 0.f;
#pragma unroll
    for (int d = 0; d < D; d++) {
        float v = x[d] * SQ2L;
        ns = fmaf(v, v, ns);
        __half h = __float2half_rn(v);
        hi[d] = h;
        lo[d] = __float2half_rn(v - __half2float(h));
    }
    uint4* out = g_S + (size_t)p * 4;
#pragma unroll
    for (int i = 0; i < 4; i++) out[i] = u[i];
    g_N[p] = -0.5f * ns;
}

// ---------------------------------------------------------------------------
// Kernel 2: pairwise 128x128 tiles, interleaved two-half epilogue + fused
// final reduction in the last CTA.
// Warp w: rows (w&3)*32 + {0,16}, cols (w>>2)*64 (two 32-col halves).
// ---------------------------------------------------------------------------
__global__ void __launch_bounds__(256, 2) pair_kernel(float* __restrict__ out) {
    extern __shared__ __align__(16) char dsm[];
    __shared__ float  sLA[TILE];
    __shared__ float  sLB[TILE];
    __shared__ float  wsum[8];
    __shared__ double sred[256];
    __shared__ unsigned int s_rank;

    const int bid  = blockIdx.x;
    const int tid  = threadIdx.x;
    const int lane = tid & 31;
    const int w    = tid >> 5;

    int ti = (int)((2.0 * TB + 1.0 - sqrt((2.0 * TB + 1.0) * (2.0 * TB + 1.0)
                                          - 8.0 * (double)bid)) * 0.5);
    while (tri_row_start(ti + 1) <= bid) ti++;
    while (tri_row_start(ti) > bid) ti--;
    const int tj = ti + (bid - tri_row_start(ti));

    // ---- build A/B tiles in SMEM (row stride 112B; conflict-free ldmatrix) ----
    {
        const int  row = tid & 127;
        const bool isA = tid < 128;
        const int  pt  = (isA ? ti : tj) * TILE + row;
        const uint4* srow = g_S + (size_t)pt * 4;
        char* rbase = dsm + (isA ? 0 : ATILEB) + row * ROWB;

        uint4 u[4];
#pragma unroll
        for (int i = 0; i < 4; i++) u[i] = srow[i];

        // A: [hi hi lo lo hi hi]    B: [hi hi hi hi lo lo]
        const int mapA[6] = {0,1, 2,3, 0,1};
        const int mapB[6] = {0,1, 0,1, 2,3};
#pragma unroll
        for (int c = 0; c < 6; c++) {
            int s = isA ? mapA[c] : mapB[c];
            *(uint4*)(rbase + c * 16) = u[s];
        }
        float e = ex2(g_N[pt]);
        if (isA) sLA[row] = e; else sLB[row] = e;
    }
    __syncthreads();

    const uint32_t sA = smem_u32(dsm);
    const uint32_t sB = sA + ATILEB;
    const int mbase = (w & 3) * 32;
    const int nbase = (w >> 2) * 64;
    const int gid = lane >> 2;
    const int tig = lane & 3;

    // ---- preload A fragments (3 kc x 2 m-tiles = 24 regs) ----
    const uint32_t aRow   = (uint32_t)(mbase + (lane & 7) + ((lane >> 3) & 1) * 8);
    const uint32_t aAddr0 = sA + aRow * ROWB + ((lane >> 4) & 1) * 16;
    const uint32_t aAddr1 = aAddr0 + 16 * ROWB;
    uint32_t a0[NKC][4], a1[NKC][4];
#pragma unroll
    for (int kc = 0; kc < NKC; kc++) {
        ldsm4(a0[kc], aAddr0 + kc * 32);
        ldsm4(a1[kc], aAddr1 + kc * 32);
    }

    const uint32_t bRowQ = (uint32_t)((lane & 7) + ((lane >> 4) & 1) * 8);
    const uint32_t bColH = ((lane >> 3) & 1) * 16;
    const uint32_t bBase = sB + (uint32_t)(nbase + bRowQ) * ROWB + bColH;

    // acc layout: acc[((mt*2+q)*2+h)*... flat: t -> mt=t>>4, ntl=(t>>2)&3, e=t&3
    float accA[32], accB[32];
#pragma unroll
    for (int i = 0; i < 32; i++) { accA[i] = 0.f; accB[i] = 0.f; }

    float p00 = 0.f, p01 = 0.f, p10 = 0.f, p11 = 0.f;   // p[mt][h]

    // ================= phase 1: n-half A (q = 0,1) =================
#pragma unroll
    for (int kc = 0; kc < NKC; kc++) {
        uint32_t b0[4], b1[4];
        ldsm4(b0, bBase + 0 * 16 * ROWB + kc * 32);
        ldsm4(b1, bBase + 1 * 16 * ROWB + kc * 32);
        mma16816(accA + 0,  a0[kc], b0[0], b0[1]);
        mma16816(accA + 4,  a0[kc], b0[2], b0[3]);
        mma16816(accA + 8,  a0[kc], b1[0], b1[1]);
        mma16816(accA + 12, a0[kc], b1[2], b1[3]);
        mma16816(accA + 16, a1[kc], b0[0], b0[1]);
        mma16816(accA + 20, a1[kc], b0[2], b0[3]);
        mma16816(accA + 24, a1[kc], b1[0], b1[1]);
        mma16816(accA + 28, a1[kc], b1[2], b1[3]);
    }

    // enb for half A (8 regs)
    float enbA[4][2];
#pragma unroll
    for (int ntl = 0; ntl < 4; ntl++) {
        int j0 = nbase + ntl * 8 + tig * 2;
        enbA[ntl][0] = sLB[j0];
        enbA[ntl][1] = sLB[j0 + 1];
    }

    // ===== phase 2: n-half B (q = 2,3) + interleaved half-A MUFU epilogue =====
    {
        const int ES[NKC + 1] = {0, 11, 22, 32};
#pragma unroll
        for (int kc = 0; kc < NKC; kc++) {
            uint32_t b2[4], b3[4];
            ldsm4(b2, bBase + 2 * 16 * ROWB + kc * 32);
            ldsm4(b3, bBase + 3 * 16 * ROWB + kc * 32);
            mma16816(accB + 0,  a0[kc], b2[0], b2[1]);
            mma16816(accB + 4,  a0[kc], b2[2], b2[3]);
            mma16816(accB + 8,  a0[kc], b3[0], b3[1]);
            mma16816(accB + 12, a0[kc], b3[2], b3[3]);
            mma16816(accB + 16, a1[kc], b2[0], b2[1]);
            mma16816(accB + 20, a1[kc], b2[2], b2[3]);
            mma16816(accB + 24, a1[kc], b3[0], b3[1]);
            mma16816(accB + 28, a1[kc], b3[2], b3[3]);
#pragma unroll
            for (int t = ES[kc]; t < ES[kc + 1]; t++) {
                const int ntl = (t >> 2) & 3, e = t & 3;
                float v = ex2(accA[t]) * enbA[ntl][e & 1];
                if (t < 16) { if ((e >> 1) == 0) p00 += v; else p01 += v; }
                else        { if ((e >> 1) == 0) p10 += v; else p11 += v; }
            }
        }
    }

    // ================= phase 3: half-B epilogue tail =================
    float enbB[4][2];
#pragma unroll
    for (int ntl = 0; ntl < 4; ntl++) {
        int j0 = nbase + 32 + ntl * 8 + tig * 2;
        enbB[ntl][0] = sLB[j0];
        enbB[ntl][1] = sLB[j0 + 1];
    }
#pragma unroll
    for (int t = 0; t < 32; t++) {
        const int ntl = (t >> 2) & 3, e = t & 3;
        float v = ex2(accB[t]) * enbB[ntl][e & 1];
        if (t < 16) { if ((e >> 1) == 0) p00 += v; else p01 += v; }
        else        { if ((e >> 1) == 0) p10 += v; else p11 += v; }
    }

    // norm-weighted combine over rows
    float tsum = p00 * sLA[mbase + gid]
               + p01 * sLA[mbase + gid + 8]
               + p10 * sLA[mbase + 16 + gid]
               + p11 * sLA[mbase + 16 + gid + 8];

#pragma unroll
    for (int off = 16; off; off >>= 1)
        tsum += __shfl_xor_sync(0xffffffffu, tsum, off);
    if (lane == 0) wsum[w] = tsum;
    __syncthreads();

    if (tid == 0) {
        double t = 0.0;
#pragma unroll
        for (int x = 0; x < 8; x++) t += (double)wsum[x];
        double wgt = (ti == tj) ? 1.0 : 2.0;
        double sgn = ((ti < TB / 2) == (tj < TB / 2)) ? 1.0 : -1.0;
        g_part[bid] = t * wgt * sgn;
        __threadfence();
        s_rank = atomicAdd(&g_count, 1u);
    }
    __syncthreads();

    // ---- last CTA: deterministic fixed-order final reduction ----
    if (s_rank == NBLK - 1) {
        const volatile double* gp = g_part;
        double t = 0.0;
        for (int i = tid; i < NBLK; i += 256) t += gp[i];
        sred[tid] = t;
        __syncthreads();
#pragma unroll
        for (int off = 128; off; off >>= 1) {
            if (tid < off) sred[tid] += sred[tid + off];
            __syncthreads();
        }
        if (tid == 0) out[0] = (float)(sred[0] / 67108864.0);   // / n^2
    }
}

// ---------------------------------------------------------------------------
extern "C" void kernel_launch(void* const* d_in, const int* in_sizes, int n_in,
                              void* d_out, int out_size) {
    const float* src = (const float*)d_in[0];
    const float* tgt = (const float*)d_in[1];

    const int smem_bytes = 2 * ATILEB;     // 28672 B
    cudaFuncSetAttribute(pair_kernel, cudaFuncAttributeMaxDynamicSharedMemorySize,
                         smem_bytes);

    split_kernel<<<NP / 128, 128>>>(src, tgt);
    pair_kernel<<<NBLK, 256, smem_bytes>>>((float*)d_out);
}

// round 12
// speedup vs baseline: 1.5001x; 1.5001x over previous
#include <cuda_runtime.h>
#include <cuda_fp16.h>
#include <math.h>
#include <stdint.h>

// ---------------------------------------------------------------------------
// MMD^2 (RBF, gamma=1), 8192x16 fp32, via mma.sync.m16n8k16 fp16 (sm_100 base).
//
// Coords scaled by sqrt(2*log2e), split x = hi + lo (fp16).
// K = 48: A chunks [hi | lo | hi], B chunks [hi | hi | lo]
//   => acc = 2*log2e*dot(a,b)  (lo*lo dropped, ~2^-22 rel)
// Epilogue: k = ex2(acc) * ena * enb, ena/enb = exp2(-0.5|x_s|^2) per row.
// CTA = 128 threads computing a 128(m) x 64(n) output tile (two per
// triangle tile) -> 4 CTAs/SM, decorrelated phases so tensor & MUFU overlap.
// Final reduction fused into the last CTA (threadfence-reduction pattern).
// ---------------------------------------------------------------------------

#define NSRC   8192
#define D      16
#define NP     16384
#define TILE   128
#define TB     (NP / TILE)                 // 128
#define NTRI   (TB * (TB + 1) / 2)         // 8256 triangle tiles
#define NBLK   (NTRI * 2)                  // 16512 CTAs (two n-halves)
#define SQ2L   1.6986436004918308f         // sqrt(2*log2(e))
#define ROWB   112                         // 96B data + 16B pad (conflict-free)
#define NKC    3                           // K = 48, chunks of 16
#define ATILEB (TILE * ROWB)               // 14336 B (A: 128 rows)
#define BTILEB (64 * ROWB)                 // 7168 B  (B: 64 rows)

// per point: u0,u1 = hi(16 fp16), u2,u3 = lo
__device__ uint4  g_S[NP * 4];
__device__ float  g_N[NP];                 // -0.5*|x_s|^2
__device__ double g_part[NBLK];
__device__ unsigned int g_count;

// ---------------- helpers ----------------
__device__ __forceinline__ float ex2(float x) {
    float r; asm("ex2.approx.f32 %0, %1;" : "=f"(r) : "f"(x)); return r;
}
__device__ __forceinline__ uint32_t smem_u32(const void* p) {
    uint32_t a;
    asm("{ .reg .u64 t; cvta.to.shared.u64 t, %1; cvt.u32.u64 %0, t; }"
        : "=r"(a) : "l"(p));
    return a;
}
__device__ __forceinline__ void ldsm4(uint32_t* r, uint32_t addr) {
    asm volatile("ldmatrix.sync.aligned.m8n8.x4.shared.b16 {%0,%1,%2,%3}, [%4];"
                 : "=r"(r[0]), "=r"(r[1]), "=r"(r[2]), "=r"(r[3]) : "r"(addr));
}
__device__ __forceinline__ void mma16816(float* c, const uint32_t* a,
                                         uint32_t b0, uint32_t b1) {
    asm volatile("mma.sync.aligned.m16n8k16.row.col.f32.f16.f16.f32 "
                 "{%0,%1,%2,%3}, {%4,%5,%6,%7}, {%8,%9}, {%0,%1,%2,%3};"
                 : "+f"(c[0]), "+f"(c[1]), "+f"(c[2]), "+f"(c[3])
                 : "r"(a[0]), "r"(a[1]), "r"(a[2]), "r"(a[3]), "r"(b0), "r"(b1));
}
__device__ __forceinline__ int tri_row_start(int t) {
    return t * TB - ((t * (t - 1)) >> 1);
}

// ---------------------------------------------------------------------------
// Kernel 1: scale, fp16 hi/lo split, norm term. Also resets g_count.
// ---------------------------------------------------------------------------
__global__ void __launch_bounds__(128) split_kernel(const float* __restrict__ src,
                                                    const float* __restrict__ tgt) {
    if (blockIdx.x == 0 && threadIdx.x == 0) g_count = 0u;
    int p = blockIdx.x * 128 + threadIdx.x;
    if (p >= NP) return;
    const float* x = (p < NSRC) ? (src + (size_t)p * D) : (tgt + (size_t)(p - NSRC) * D);

    uint4 u[4];
    __half* hi = (__half*)&u[0];
    __half* lo = (__half*)&u[2];

    float ns = 0.f;
#pragma unroll
    for (int d = 0; d < D; d++) {
        float v = x[d] * SQ2L;
        ns = fmaf(v, v, ns);
        __half h = __float2half_rn(v);
        hi[d] = h;
        lo[d] = __float2half_rn(v - __half2float(h));
    }
    uint4* out = g_S + (size_t)p * 4;
#pragma unroll
    for (int i = 0; i < 4; i++) out[i] = u[i];
    g_N[p] = -0.5f * ns;
}

// ---------------------------------------------------------------------------
// Kernel 2: 128x64 output tile per CTA (128 threads, 4 warps).
// Warp w: rows w*32 + {0,16}, all 64 n-cols (8 n8-tiles).
// ---------------------------------------------------------------------------
__global__ void __launch_bounds__(128, 4) pair_kernel(float* __restrict__ out) {
    extern __shared__ __align__(16) char dsm[];
    __shared__ float  sLA[TILE];
    __shared__ float  sLB[64];
    __shared__ float  wsum[4];
    __shared__ double sred[128];
    __shared__ unsigned int s_rank;

    const int bid  = blockIdx.x;
    const int tid  = threadIdx.x;
    const int lane = tid & 31;
    const int w    = tid >> 5;

    const int tri   = bid >> 1;
    const int nhalf = bid & 1;

    int ti = (int)((2.0 * TB + 1.0 - sqrt((2.0 * TB + 1.0) * (2.0 * TB + 1.0)
                                          - 8.0 * (double)tri)) * 0.5);
    while (tri_row_start(ti + 1) <= tri) ti++;
    while (tri_row_start(ti) > tri) ti--;
    const int tj = ti + (tri - tri_row_start(ti));

    // ---- build A (128 rows) and B (64 rows) tiles in SMEM ----
    {
        const int pa = ti * TILE + tid;                 // A row for this thread
        const uint4* sra = g_S + (size_t)pa * 4;
        char* rba = dsm + tid * ROWB;
        uint4 ua[4];
#pragma unroll
        for (int i = 0; i < 4; i++) ua[i] = sra[i];
        // A: [hi hi lo lo hi hi]
        const int mapA[6] = {0,1, 2,3, 0,1};
#pragma unroll
        for (int c = 0; c < 6; c++)
            *(uint4*)(rba + c * 16) = ua[mapA[c]];
        sLA[tid] = ex2(g_N[pa]);

        if (tid < 64) {
            const int pb = tj * TILE + nhalf * 64 + tid;  // B row
            const uint4* srb = g_S + (size_t)pb * 4;
            char* rbb = dsm + ATILEB + tid * ROWB;
            uint4 ub[4];
#pragma unroll
            for (int i = 0; i < 4; i++) ub[i] = srb[i];
            // B: [hi hi hi hi lo lo]
            const int mapB[6] = {0,1, 0,1, 2,3};
#pragma unroll
            for (int c = 0; c < 6; c++)
                *(uint4*)(rbb + c * 16) = ub[mapB[c]];
            sLB[tid] = ex2(g_N[pb]);
        }
    }
    __syncthreads();

    const uint32_t sA = smem_u32(dsm);
    const uint32_t sB = sA + ATILEB;
    const int mbase = w * 32;
    const int gid = lane >> 2;
    const int tig = lane & 3;

    // ---- preload A fragments (3 kc x 2 m-tiles = 24 regs) ----
    const uint32_t aRow   = (uint32_t)(mbase + (lane & 7) + ((lane >> 3) & 1) * 8);
    const uint32_t aAddr0 = sA + aRow * ROWB + ((lane >> 4) & 1) * 16;
    const uint32_t aAddr1 = aAddr0 + 16 * ROWB;
    uint32_t a0[NKC][4], a1[NKC][4];
#pragma unroll
    for (int kc = 0; kc < NKC; kc++) {
        ldsm4(a0[kc], aAddr0 + kc * 32);
        ldsm4(a1[kc], aAddr1 + kc * 32);
    }

    const uint32_t bRowQ = (uint32_t)((lane & 7) + ((lane >> 4) & 1) * 8);
    const uint32_t bColH = ((lane >> 3) & 1) * 16;
    uint32_t bAddr[4];
#pragma unroll
    for (int q = 0; q < 4; q++)
        bAddr[q] = sB + (uint32_t)(16 * q + bRowQ) * ROWB + bColH;

    float acc[2][8][4];
#pragma unroll
    for (int mt = 0; mt < 2; mt++)
#pragma unroll
        for (int nt = 0; nt < 8; nt++)
#pragma unroll
            for (int e = 0; e < 4; e++) acc[mt][nt][e] = 0.f;

#pragma unroll
    for (int kc = 0; kc < NKC; kc++) {
        const uint32_t ko = kc * 32;
        uint32_t b[4][4];
#pragma unroll
        for (int q = 0; q < 4; q++) ldsm4(b[q], bAddr[q] + ko);
#pragma unroll
        for (int nt = 0; nt < 8; nt++) {
            const uint32_t b0 = b[nt >> 1][(nt & 1) * 2];
            const uint32_t b1 = b[nt >> 1][(nt & 1) * 2 + 1];
            mma16816(acc[0][nt], a0[kc], b0, b1);
            mma16816(acc[1][nt], a1[kc], b0, b1);
        }
    }

    // ---- epilogue: k = ex2(acc) * ena * enb; sum over tile ----
    float ena[2][2];
#pragma unroll
    for (int mt = 0; mt < 2; mt++)
#pragma unroll
        for (int h = 0; h < 2; h++)
            ena[mt][h] = sLA[mbase + mt * 16 + gid + h * 8];

    float enb[8][2];
#pragma unroll
    for (int nt = 0; nt < 8; nt++) {
        int j0 = nt * 8 + tig * 2;
        enb[nt][0] = sLB[j0];
        enb[nt][1] = sLB[j0 + 1];
    }

    float p[2][2] = {{0.f, 0.f}, {0.f, 0.f}};
#pragma unroll
    for (int mt = 0; mt < 2; mt++)
#pragma unroll
        for (int nt = 0; nt < 8; nt++)
#pragma unroll
            for (int e = 0; e < 4; e++)
                p[mt][e >> 1] = fmaf(ex2(acc[mt][nt][e]), enb[nt][e & 1],
                                     p[mt][e >> 1]);

    float tsum = 0.f;
#pragma unroll
    for (int mt = 0; mt < 2; mt++)
#pragma unroll
        for (int h = 0; h < 2; h++)
            tsum = fmaf(p[mt][h], ena[mt][h], tsum);

#pragma unroll
    for (int off = 16; off; off >>= 1)
        tsum += __shfl_xor_sync(0xffffffffu, tsum, off);
    if (lane == 0) wsum[w] = tsum;
    __syncthreads();

    if (tid == 0) {
        double t = (double)wsum[0] + (double)wsum[1]
                 + (double)wsum[2] + (double)wsum[3];
        double wgt = (ti == tj) ? 1.0 : 2.0;
        double sgn = ((ti < TB / 2) == (tj < TB / 2)) ? 1.0 : -1.0;
        g_part[bid] = t * wgt * sgn;
        __threadfence();
        s_rank = atomicAdd(&g_count, 1u);
    }
    __syncthreads();

    // ---- last CTA: deterministic fixed-order final reduction ----
    if (s_rank == NBLK - 1) {
        const volatile double* gp = g_part;
        double t = 0.0;
        for (int i = tid; i < NBLK; i += 128) t += gp[i];
        sred[tid] = t;
        __syncthreads();
#pragma unroll
        for (int off = 64; off; off >>= 1) {
            if (tid < off) sred[tid] += sred[tid + off];
            __syncthreads();
        }
        if (tid == 0) out[0] = (float)(sred[0] / 67108864.0);   // / n^2
    }
}

// ---------------------------------------------------------------------------
extern "C" void kernel_launch(void* const* d_in, const int* in_sizes, int n_in,
                              void* d_out, int out_size) {
    const float* src = (const float*)d_in[0];
    const float* tgt = (const float*)d_in[1];

    const int smem_bytes = ATILEB + BTILEB;     // 21504 B
    cudaFuncSetAttribute(pair_kernel, cudaFuncAttributeMaxDynamicSharedMemorySize,
                         smem_bytes);

    split_kernel<<<NP / 128, 128>>>(src, tgt);
    pair_kernel<<<NBLK, 128, smem_bytes>>>((float*)d_out);
}